// round 1
// baseline (speedup 1.0000x reference)
#include <cuda_runtime.h>
#include <math.h>
#include <float.h>

// Shapes (fixed for this problem)
//  MSA_emb: (1, 512, 768, 256) fp32   seq_mask: (1, 512) int32
//  Wq, Wk: (256, 256) fp32            out: (1, 512, 768, 8, 1) fp32
#define R_DIM 512
#define C_DIM 768
#define D_DIM 256
#define H_DIM 8
#define HD_DIM 32
static constexpr float SCALE = 0.17677669529663687f; // 1/sqrt(32)

// Scratch (device globals; no allocation allowed)
__device__ float g_Q[C_DIM * 256];          // Q[c][o], already scaled
__device__ float g_P[C_DIM * H_DIM * D_DIM]; // P[c][h][e]

// ---------------------------------------------------------------------------
// Kernel 1: Q = SCALE * (MSA[0,0,:,:] @ Wq^T)      (768x256) = (768x256)(256x256)
// grid 96 = 24 c-tiles (32 rows) x 4 o-tiles (64 cols), 256 threads
// ---------------------------------------------------------------------------
__global__ void kQ(const float* __restrict__ msa, const float* __restrict__ wq) {
    __shared__ float xs[32][256];
    const int cb  = blockIdx.x >> 2;
    const int ob  = blockIdx.x & 3;
    const int tid = threadIdx.x;

    for (int i = tid; i < 32 * 64; i += 256) {
        int row = i >> 6, col = i & 63;
        reinterpret_cast<float4*>(&xs[row][col * 4])[0] =
            reinterpret_cast<const float4*>(msa + (cb * 32 + row) * 256 + col * 4)[0];
    }
    __syncthreads();

    const int o  = ob * 64 + (tid & 63);
    const int cg = tid >> 6;               // 4 groups of 8 c-rows
    float acc[8] = {0, 0, 0, 0, 0, 0, 0, 0};
    const float4* wrow = reinterpret_cast<const float4*>(wq + o * 256);
    for (int f4 = 0; f4 < 64; f4++) {
        float4 w = __ldg(&wrow[f4]);
        int f = f4 * 4;
#pragma unroll
        for (int j = 0; j < 8; j++) {
            int c = cg * 8 + j;
            acc[j] += w.x * xs[c][f] + w.y * xs[c][f + 1] +
                      w.z * xs[c][f + 2] + w.w * xs[c][f + 3];
        }
    }
#pragma unroll
    for (int j = 0; j < 8; j++)
        g_Q[(cb * 32 + cg * 8 + j) * 256 + o] = acc[j] * SCALE;
}

// ---------------------------------------------------------------------------
// Kernel 2: P[c][h][e] = sum_{d<32} Q[c][h*32+d] * Wk[h*32+d][e]
// grid 192 = 24 c-tiles (32 rows) x 8 heads, 256 threads (thread = one e)
// ---------------------------------------------------------------------------
__global__ void kP(const float* __restrict__ wk) {
    const int cb  = blockIdx.x >> 3;
    const int h   = blockIdx.x & 7;
    const int tid = threadIdx.x;

    __shared__ float qs[32][33];
    __shared__ float wks[32 * 256];

    for (int i = tid; i < 1024; i += 256)
        qs[i >> 5][i & 31] = g_Q[(cb * 32 + (i >> 5)) * 256 + h * 32 + (i & 31)];
    for (int i = tid; i < 8192; i += 256)
        wks[i] = wk[(h * 32 + (i >> 8)) * 256 + (i & 255)];
    __syncthreads();

    float acc[32];
#pragma unroll
    for (int c = 0; c < 32; c++) acc[c] = 0.f;
    for (int d = 0; d < 32; d++) {
        float w = wks[d * 256 + tid];
#pragma unroll
        for (int c = 0; c < 32; c++) acc[c] += qs[c][d] * w;
    }
#pragma unroll
    for (int c = 0; c < 32; c++)
        g_P[(cb * 32 + c) * (H_DIM * D_DIM) + h * 256 + tid] = acc[c];
}

// ---------------------------------------------------------------------------
// Kernel 3 (main): per-c block.  QK[h][r] = sum_e P[c][h][e]*MSA[r][c][e],
// masked softmax over r, transposed write out[r*6144 + c*8 + h].
// 768 blocks, 256 threads = 8 warps (warp per head).
// ---------------------------------------------------------------------------
static constexpr int XS_STRIDE = 260;  // 64-row x-tile, padded: conflict-free LDS.128
static constexpr int QK_STRIDE = 516;  // (h,r)->bank bijection for transposed read

__global__ void kMain(const float* __restrict__ msa,
                      const int* __restrict__ mask,
                      float* __restrict__ out) {
    extern __shared__ float sm[];
    float* xs   = sm;                          // 64 * 260
    float* qk   = xs + 64 * XS_STRIDE;         // 8 * 516
    float* ps   = qk + 8 * QK_STRIDE;          // 2048
    float* sinv = ps + 2048;                   // 8
    int*   msk  = (int*)(sinv + 8);            // 512

    const int c    = blockIdx.x;
    const int tid  = threadIdx.x;
    const int h    = tid >> 5;
    const int lane = tid & 31;

    for (int i = tid; i < 2048; i += 256) ps[i] = g_P[c * 2048 + i];
    for (int i = tid; i < 512; i += 256)  msk[i] = mask[i];

    for (int t = 0; t < 8; t++) {
        __syncthreads();   // xs safe to overwrite (also covers ps/msk on t==0)
        // stage 64 rows of MSA[:, c, :] (each row 1KB contiguous)
        for (int i = tid; i < 64 * 64; i += 256) {
            int rl = i >> 6, col = i & 63;
            reinterpret_cast<float4*>(&xs[rl * XS_STRIDE + col * 4])[0] =
                reinterpret_cast<const float4*>(
                    msa + ((size_t)(t * 64 + rl) * C_DIM + c) * 256 + col * 4)[0];
        }
        __syncthreads();

        float acc0 = 0.f, acc1 = 0.f;
        const float* xrow0 = xs + lane * XS_STRIDE;
        const float* xrow1 = xs + (lane + 32) * XS_STRIDE;
#pragma unroll
        for (int ch = 0; ch < 8; ch++) {
            float4 p[8];
            const float4* pp = reinterpret_cast<const float4*>(ps + h * 256 + ch * 32);
#pragma unroll
            for (int i = 0; i < 8; i++) p[i] = pp[i];  // warp-uniform broadcast
            const float4* x0 = reinterpret_cast<const float4*>(xrow0 + ch * 32);
            const float4* x1 = reinterpret_cast<const float4*>(xrow1 + ch * 32);
#pragma unroll
            for (int i = 0; i < 8; i++) {
                float4 a = x0[i];
                acc0 += p[i].x * a.x + p[i].y * a.y + p[i].z * a.z + p[i].w * a.w;
            }
#pragma unroll
            for (int i = 0; i < 8; i++) {
                float4 b = x1[i];
                acc1 += p[i].x * b.x + p[i].y * b.y + p[i].z * b.z + p[i].w * b.w;
            }
        }
        qk[h * QK_STRIDE + t * 64 + lane]      = acc0;
        qk[h * QK_STRIDE + t * 64 + 32 + lane] = acc1;
    }
    __syncthreads();

    // --- masked softmax over r (warp h owns head h) ---
    float vals[16];
    float mx = -FLT_MAX;
#pragma unroll
    for (int j = 0; j < 16; j++) {
        int r = lane + 32 * j;
        float v = (msk[r] != 0) ? qk[h * QK_STRIDE + r] : -FLT_MAX;
        vals[j] = v;
        mx = fmaxf(mx, v);
    }
#pragma unroll
    for (int s = 16; s; s >>= 1) mx = fmaxf(mx, __shfl_xor_sync(0xffffffffu, mx, s));

    float sum = 0.f;
#pragma unroll
    for (int j = 0; j < 16; j++) {
        int r = lane + 32 * j;
        float e = (msk[r] != 0) ? __expf(vals[j] - mx) : 0.f;
        sum += e;
        qk[h * QK_STRIDE + r] = e;
    }
#pragma unroll
    for (int s = 16; s; s >>= 1) sum += __shfl_xor_sync(0xffffffffu, sum, s);
    if (lane == 0) sinv[h] = 1.f / sum;
    __syncthreads();

    // --- transposed write: out[r*6144 + c*8 + h], 32B contiguous per r ---
#pragma unroll
    for (int k = 0; k < 16; k++) {
        int idx = tid + 256 * k;     // 0..4095 = 512 r x 8 h
        int r = idx >> 3, hh = idx & 7;
        out[(size_t)r * (C_DIM * H_DIM) + c * H_DIM + hh] =
            qk[hh * QK_STRIDE + r] * sinv[hh];
    }
}

// ---------------------------------------------------------------------------
extern "C" void kernel_launch(void* const* d_in, const int* in_sizes, int n_in,
                              void* d_out, int out_size) {
    const float* msa  = (const float*)d_in[0];
    const int*   mask = (const int*)d_in[1];
    const float* wq   = (const float*)d_in[2];
    const float* wk   = (const float*)d_in[3];
    float* out = (float*)d_out;

    const size_t smem = (64 * XS_STRIDE + 8 * QK_STRIDE + 2048 + 8) * sizeof(float)
                        + 512 * sizeof(int);   // 93,344 B
    cudaFuncSetAttribute(kMain, cudaFuncAttributeMaxDynamicSharedMemorySize, (int)smem);

    kQ<<<96, 256>>>(msa, wq);
    kP<<<192, 256>>>(wk);
    kMain<<<768, 256, smem>>>(msa, mask, out);
}

// round 3
// speedup vs baseline: 1.0676x; 1.0676x over previous
#include <cuda_runtime.h>
#include <math.h>
#include <float.h>

// Shapes (fixed): MSA_emb (1,512,768,256) f32; seq_mask (1,512) i32;
// Wq,Wk (256,256) f32; out (1,512,768,8,1) f32
#define R_DIM 512
#define C_DIM 768
#define D_DIM 256
#define H_DIM 8
static constexpr float SCALE = 0.17677669529663687f; // 1/sqrt(32)

// P[c][e][h] (h-major so 8 head coeffs are one 32B chunk)
__device__ float g_P[C_DIM * D_DIM * H_DIM];

// ---- packed f32x2 helpers (Blackwell): b64 regs, "l" constraint ----
typedef unsigned long long u64;
__device__ __forceinline__ u64 ffma2(u64 a, u64 b, u64 c) {
    u64 d;
    asm("fma.rn.f32x2 %0, %1, %2, %3;" : "=l"(d) : "l"(a), "l"(b), "l"(c));
    return d;
}
__device__ __forceinline__ u64 pack2(float x, float y) {
    u64 d; asm("mov.b64 %0, {%1, %2};" : "=l"(d) : "f"(x), "f"(y)); return d;
}
__device__ __forceinline__ void unpack2(u64 d, float& x, float& y) {
    asm("mov.b64 {%0, %1}, %2;" : "=f"(x), "=f"(y) : "l"(d));
}

// ---------------------------------------------------------------------------
// kQP: fused Q = SCALE*(msa0 @ Wq^T) then P[c][e][h] = sum_d Q[c][h*32+d]*Wk[h*32+d][e]
// grid 192 (4 c per block), 256 threads.
// ---------------------------------------------------------------------------
__global__ void __launch_bounds__(256) kQP(const float* __restrict__ msa,
                                           const float* __restrict__ wq,
                                           const float* __restrict__ wk) {
    __shared__ float xs[4][256];
    __shared__ float qs[4][257];
    __shared__ float pbuf[4 * 2048];   // [cc][e][h]
    const int c0  = blockIdx.x * 4;
    const int tid = threadIdx.x;

    // stage 4 query rows msa[0, 0, c0+cc, :]
    for (int i = tid; i < 4 * 64; i += 256) {
        int cc = i >> 6, f4 = i & 63;
        reinterpret_cast<float4*>(&xs[cc][f4 * 4])[0] =
            reinterpret_cast<const float4*>(msa + (size_t)(c0 + cc) * 256)[f4];
    }
    __syncthreads();

    // Q: thread = output o = tid
    {
        float acc[4] = {0.f, 0.f, 0.f, 0.f};
        const float4* wrow = reinterpret_cast<const float4*>(wq + (size_t)tid * 256);
#pragma unroll 8
        for (int f4 = 0; f4 < 64; f4++) {
            float4 w = wrow[f4];
#pragma unroll
            for (int cc = 0; cc < 4; cc++) {
                const float* x = &xs[cc][f4 * 4];
                acc[cc] += w.x * x[0] + w.y * x[1] + w.z * x[2] + w.w * x[3];
            }
        }
#pragma unroll
        for (int cc = 0; cc < 4; cc++) qs[cc][tid] = acc[cc] * SCALE;
    }
    __syncthreads();

    // P: thread = e = tid; Wk reads coalesced across threads
    for (int h = 0; h < 8; h++) {
        float a[4] = {0.f, 0.f, 0.f, 0.f};
#pragma unroll 8
        for (int d = 0; d < 32; d++) {
            float w = wk[(size_t)(h * 32 + d) * 256 + tid];
#pragma unroll
            for (int cc = 0; cc < 4; cc++) a[cc] += qs[cc][h * 32 + d] * w;
        }
#pragma unroll
        for (int cc = 0; cc < 4; cc++)
            pbuf[cc * 2048 + tid * 8 + h] = a[cc];
    }
    __syncthreads();

    // coalesced store of 4 c-slices (32 KB)
    float4* gp = reinterpret_cast<float4*>(g_P + (size_t)c0 * 2048);
    const float4* pb = reinterpret_cast<const float4*>(pbuf);
    for (int i = tid; i < 2048; i += 256) gp[i] = pb[i];
}

// ---------------------------------------------------------------------------
// kMain: block per c (768 blocks, 128 threads). Thread owns 4 rows, streams
// x straight from DRAM (no smem staging), 8 heads packed as 4 f32x2 pairs.
// Then warp-per-2-heads masked softmax + transposed write.
// ---------------------------------------------------------------------------
static constexpr int QK_STRIDE = 516;

__global__ void __launch_bounds__(128, 6) kMain(const float* __restrict__ msa,
                                                const int* __restrict__ mask,
                                                float* __restrict__ out) {
    __shared__ __align__(16) float ps[2048];       // P[c][e][h]
    __shared__ float qk[8 * QK_STRIDE];
    __shared__ float sinv[8];
    __shared__ int   msk[512];

    const int c    = blockIdx.x;
    const int tid  = threadIdx.x;
    const int lane = tid & 31;

    {
        float4* p4 = reinterpret_cast<float4*>(ps);
        const float4* g4 = reinterpret_cast<const float4*>(g_P + (size_t)c * 2048);
        for (int i = tid; i < 512; i += 128) p4[i] = g4[i];
        for (int i = tid; i < 512; i += 128) msk[i] = mask[i];
    }
    __syncthreads();

    // 4 rows per thread: r = tid*4 + k
    const float4* xr[4];
#pragma unroll
    for (int k = 0; k < 4; k++)
        xr[k] = reinterpret_cast<const float4*>(
            msa + ((size_t)(tid * 4 + k) * C_DIM + c) * 256);

    const ulonglong2* pd = reinterpret_cast<const ulonglong2*>(ps);

    u64 acc[4][4];   // [row k][head pair p]
#pragma unroll
    for (int k = 0; k < 4; k++)
#pragma unroll
        for (int p = 0; p < 4; p++) acc[k][p] = pack2(0.f, 0.f);

#pragma unroll 4
    for (int e4 = 0; e4 < 64; e4++) {
        float4 xv[4];
#pragma unroll
        for (int k = 0; k < 4; k++) xv[k] = xr[k][e4];
        float xf[4][4];
#pragma unroll
        for (int k = 0; k < 4; k++) {
            xf[k][0] = xv[k].x; xf[k][1] = xv[k].y;
            xf[k][2] = xv[k].z; xf[k][3] = xv[k].w;
        }
#pragma unroll
        for (int j = 0; j < 4; j++) {
            int e = e4 * 4 + j;
            ulonglong2 pA = pd[e * 2];       // (h0,h1),(h2,h3)
            ulonglong2 pB = pd[e * 2 + 1];   // (h4,h5),(h6,h7)
#pragma unroll
            for (int k = 0; k < 4; k++) {
                u64 dx = pack2(xf[k][j], xf[k][j]);
                acc[k][0] = ffma2(pA.x, dx, acc[k][0]);
                acc[k][1] = ffma2(pA.y, dx, acc[k][1]);
                acc[k][2] = ffma2(pB.x, dx, acc[k][2]);
                acc[k][3] = ffma2(pB.y, dx, acc[k][3]);
            }
        }
    }

    // scatter to qk[h][r]
#pragma unroll
    for (int k = 0; k < 4; k++) {
        int r = tid * 4 + k;
#pragma unroll
        for (int p = 0; p < 4; p++) {
            float v0, v1;
            unpack2(acc[k][p], v0, v1);
            qk[(2 * p) * QK_STRIDE + r]     = v0;
            qk[(2 * p + 1) * QK_STRIDE + r] = v1;
        }
    }
    __syncthreads();

    // masked softmax over r: warp w handles heads 2w, 2w+1
#pragma unroll
    for (int hh = 0; hh < 2; hh++) {
        int h = (tid >> 5) * 2 + hh;
        float vals[16];
        float mx = -FLT_MAX;
#pragma unroll
        for (int j = 0; j < 16; j++) {
            int r = lane + 32 * j;
            float v = (msk[r] != 0) ? qk[h * QK_STRIDE + r] : -FLT_MAX;
            vals[j] = v;
            mx = fmaxf(mx, v);
        }
#pragma unroll
        for (int s = 16; s; s >>= 1) mx = fmaxf(mx, __shfl_xor_sync(0xffffffffu, mx, s));
        float sum = 0.f;
#pragma unroll
        for (int j = 0; j < 16; j++) {
            int r = lane + 32 * j;
            float e = (msk[r] != 0) ? __expf(vals[j] - mx) : 0.f;
            sum += e;
            qk[h * QK_STRIDE + r] = e;
        }
#pragma unroll
        for (int s = 16; s; s >>= 1) sum += __shfl_xor_sync(0xffffffffu, sum, s);
        if (lane == 0) sinv[h] = 1.f / sum;
    }
    __syncthreads();

    // transposed write: out[r*6144 + c*8 + h] (32B contiguous per r)
#pragma unroll
    for (int k = 0; k < 32; k++) {
        int idx = tid + 128 * k;          // 0..4095 = 512 r x 8 h
        int r = idx >> 3, h = idx & 7;
        out[(size_t)r * (C_DIM * H_DIM) + c * H_DIM + h] =
            qk[h * QK_STRIDE + r] * sinv[h];
    }
}

// ---------------------------------------------------------------------------
extern "C" void kernel_launch(void* const* d_in, const int* in_sizes, int n_in,
                              void* d_out, int out_size) {
    const float* msa  = (const float*)d_in[0];
    const int*   mask = (const int*)d_in[1];
    const float* wq   = (const float*)d_in[2];
    const float* wk   = (const float*)d_in[3];
    float* out = (float*)d_out;

    kQP<<<192, 256>>>(msa, wq, wk);
    kMain<<<768, 128>>>(msa, mask, out);
}

// round 6
// speedup vs baseline: 1.5965x; 1.4954x over previous
#include <cuda_runtime.h>
#include <stdint.h>
#include <math.h>
#include <float.h>

// Shapes (fixed): MSA_emb (1,512,768,256) f32; seq_mask (1,512) i32;
// Wq,Wk (256,256) f32; out (1,512,768,8,1) f32
#define R_DIM 512
#define C_DIM 768
#define H_DIM 8
static constexpr float SCALE = 0.17677669529663687f; // 1/sqrt(32)

typedef unsigned long long u64;

// P[c][e][h] (h-major: 8 head coeffs = one 32B chunk)
__device__ float g_P[C_DIM * 2048];

// ---- packed f32x2 helpers (b64 regs) ----
__device__ __forceinline__ u64 ffma2(u64 a, u64 b, u64 c) {
    u64 d;
    asm("fma.rn.f32x2 %0, %1, %2, %3;" : "=l"(d) : "l"(a), "l"(b), "l"(c));
    return d;
}
__device__ __forceinline__ u64 padd2(u64 a, u64 b) {
    u64 d;
    asm("add.rn.f32x2 %0, %1, %2;" : "=l"(d) : "l"(a), "l"(b));
    return d;
}
__device__ __forceinline__ u64 pack2(float x, float y) {
    u64 d; asm("mov.b64 %0, {%1, %2};" : "=l"(d) : "f"(x), "f"(y)); return d;
}
__device__ __forceinline__ void unpack2(u64 d, float& x, float& y) {
    asm("mov.b64 {%0, %1}, %2;" : "=f"(x), "=f"(y) : "l"(d));
}
__device__ __forceinline__ void cpasync16(unsigned int dst, const void* src) {
    asm volatile("cp.async.cg.shared.global [%0], [%1], 16;\n" :: "r"(dst), "l"(src));
}

// ---------------------------------------------------------------------------
// kQP: Q = SCALE*(msa0 @ Wq^T); P[c][e][h] = sum_d Q[c][h*32+d]*Wk[h*32+d][e]
// grid 128 (6 c per block), 256 threads, dynamic smem 61,440 B
// ---------------------------------------------------------------------------
__global__ void __launch_bounds__(256) kQP(const float* __restrict__ msa,
                                           const float* __restrict__ wq,
                                           const float* __restrict__ wk) {
    extern __shared__ float smq[];
    float* xs   = smq;            // [6][256]
    float* qs   = xs + 6 * 256;   // [6][256]
    float* pbuf = qs + 6 * 256;   // [6][2048]
    const int c0  = blockIdx.x * 6;
    const int tid = threadIdx.x;

    for (int i = tid; i < 6 * 64; i += 256) {
        int cc = i >> 6, f4 = i & 63;
        reinterpret_cast<float4*>(&xs[cc * 256 + f4 * 4])[0] =
            reinterpret_cast<const float4*>(msa + (size_t)(c0 + cc) * 256)[f4];
    }
    __syncthreads();

    {   // Q: thread = output o = tid
        float acc[6] = {0, 0, 0, 0, 0, 0};
        const float4* wrow = reinterpret_cast<const float4*>(wq + (size_t)tid * 256);
#pragma unroll 8
        for (int f4 = 0; f4 < 64; f4++) {
            float4 w = __ldg(&wrow[f4]);
#pragma unroll
            for (int cc = 0; cc < 6; cc++) {
                const float* x = &xs[cc * 256 + f4 * 4];
                acc[cc] += w.x * x[0] + w.y * x[1] + w.z * x[2] + w.w * x[3];
            }
        }
#pragma unroll
        for (int cc = 0; cc < 6; cc++) qs[cc * 256 + tid] = acc[cc] * SCALE;
    }
    __syncthreads();

    // P: thread = e = tid (Wk reads coalesced across tid)
    for (int h = 0; h < 8; h++) {
        float a[6] = {0, 0, 0, 0, 0, 0};
#pragma unroll 8
        for (int d = 0; d < 32; d++) {
            float w = __ldg(&wk[(size_t)(h * 32 + d) * 256 + tid]);
#pragma unroll
            for (int cc = 0; cc < 6; cc++) a[cc] += qs[cc * 256 + h * 32 + d] * w;
        }
#pragma unroll
        for (int cc = 0; cc < 6; cc++) pbuf[cc * 2048 + tid * 8 + h] = a[cc];
    }
    __syncthreads();

    float4* gp = reinterpret_cast<float4*>(g_P + (size_t)c0 * 2048);
    const float4* pb = reinterpret_cast<const float4*>(pbuf);
    for (int i = tid; i < 3072; i += 256) gp[i] = pb[i];
}

// ---------------------------------------------------------------------------
// kMain: block per c. 16 tiles x 32 rows, double-buffered cp.async staging.
// Thread = (row in tile = tid&31, e-eighth = tid>>5). Packed f32x2 over head
// pairs; per-tile partial combine; masked softmax; transposed write.
// 768 blocks, 256 threads, dynamic smem 102,048 B (2 blocks/SM).
// ---------------------------------------------------------------------------
static constexpr int XS_STRIDE = 260;    // lane-stride 16B mod 128B: conflict-free
static constexpr int QKS = 516;
static constexpr int TILE_F = 32 * XS_STRIDE;  // 8320 floats per buffer

__global__ void __launch_bounds__(256) kMain(const float* __restrict__ msa,
                                             const int* __restrict__ mask,
                                             float* __restrict__ out) {
    extern __shared__ float sm[];
    float* xs   = sm;                       // 2 * 8320
    float* ps   = sm + 2 * TILE_F;          // 2048
    float* qk   = ps + 2048;                // 8*516
    u64*   part = (u64*)(qk + 8 * QKS);     // 32*34 u64 (stride 34: 16B aligned rows)
    int*   msk  = (int*)(qk + 8 * QKS + 2176);
    float* sinv = (float*)(msk + 512);

    const int c    = blockIdx.x;
    const int tid  = threadIdx.x;
    const int lane = tid & 31;
    const int row  = tid & 31;   // row within tile
    const int eq   = tid >> 5;   // e-eighth (warp-uniform)

    const unsigned int xs_s = (unsigned int)__cvta_generic_to_shared(xs);

    // prefetch tiles 0,1 (coalesced 16B cp.async)
#pragma unroll
    for (int t = 0; t < 2; t++) {
        for (int k = 0; k < 8; k++) {
            int i = tid + k * 256;           // 0..2047
            int r = i >> 6, col = i & 63;
            cpasync16(xs_s + (unsigned int)((t * TILE_F + r * XS_STRIDE + col * 4) * 4),
                      msa + ((size_t)(t * 32 + r) * C_DIM + c) * 256 + col * 4);
        }
        asm volatile("cp.async.commit_group;");
    }
    {   // P slice + mask (overlaps with prefetch)
        float4* p4 = reinterpret_cast<float4*>(ps);
        const float4* g4 = reinterpret_cast<const float4*>(g_P + (size_t)c * 2048);
        for (int i = tid; i < 512; i += 256) p4[i] = g4[i];
        for (int i = tid; i < 512; i += 256) msk[i] = mask[i];
    }

    const ulonglong2* pd = reinterpret_cast<const ulonglong2*>(ps);

    for (int t = 0; t < 16; t++) {
        if (t < 15) asm volatile("cp.async.wait_group 1;");
        else        asm volatile("cp.async.wait_group 0;");
        __syncthreads();

        // compute partial QK for (row, e-range [eq*32, eq*32+32))
        const float* xrow = xs + (t & 1) * TILE_F + row * XS_STRIDE + eq * 32;
        const float4* x4 = reinterpret_cast<const float4*>(xrow);
        u64 a0 = 0, a1 = 0, a2 = 0, a3 = 0;   // +0.0f pairs
#pragma unroll
        for (int i = 0; i < 8; i++) {
            float4 xv = x4[i];
            int e0 = eq * 32 + i * 4;
            {
                ulonglong2 pA = pd[e0 * 2], pB = pd[e0 * 2 + 1];
                u64 dx = pack2(xv.x, xv.x);
                a0 = ffma2(pA.x, dx, a0); a1 = ffma2(pA.y, dx, a1);
                a2 = ffma2(pB.x, dx, a2); a3 = ffma2(pB.y, dx, a3);
            }
            {
                ulonglong2 pA = pd[(e0 + 1) * 2], pB = pd[(e0 + 1) * 2 + 1];
                u64 dx = pack2(xv.y, xv.y);
                a0 = ffma2(pA.x, dx, a0); a1 = ffma2(pA.y, dx, a1);
                a2 = ffma2(pB.x, dx, a2); a3 = ffma2(pB.y, dx, a3);
            }
            {
                ulonglong2 pA = pd[(e0 + 2) * 2], pB = pd[(e0 + 2) * 2 + 1];
                u64 dx = pack2(xv.z, xv.z);
                a0 = ffma2(pA.x, dx, a0); a1 = ffma2(pA.y, dx, a1);
                a2 = ffma2(pB.x, dx, a2); a3 = ffma2(pB.y, dx, a3);
            }
            {
                ulonglong2 pA = pd[(e0 + 3) * 2], pB = pd[(e0 + 3) * 2 + 1];
                u64 dx = pack2(xv.w, xv.w);
                a0 = ffma2(pA.x, dx, a0); a1 = ffma2(pA.y, dx, a1);
                a2 = ffma2(pB.x, dx, a2); a3 = ffma2(pB.y, dx, a3);
            }
        }
        u64* pw = part + row * 34 + eq * 4;
        pw[0] = a0; pw[1] = a1; pw[2] = a2; pw[3] = a3;
        __syncthreads();

        // prefetch tile t+2 into the buffer just consumed
        if (t < 14) {
            int tn = t + 2;
            for (int k = 0; k < 8; k++) {
                int i = tid + k * 256;
                int r = i >> 6, col = i & 63;
                cpasync16(xs_s + (unsigned int)(((tn & 1) * TILE_F + r * XS_STRIDE + col * 4) * 4),
                          msa + ((size_t)(tn * 32 + r) * C_DIM + c) * 256 + col * 4);
            }
            asm volatile("cp.async.commit_group;");
        }

        // combine 8 e-partials -> qk (128 threads: row x head-pair)
        if (tid < 128) {
            int rr = tid >> 2, p = tid & 3;
            const u64* pr = part + rr * 34 + p;
            u64 s = pr[0];
#pragma unroll
            for (int e2 = 1; e2 < 8; e2++) s = padd2(s, pr[e2 * 4]);
            float v0, v1;
            unpack2(s, v0, v1);
            int R = t * 32 + rr;
            qk[(2 * p) * QKS + R]     = v0;
            qk[(2 * p + 1) * QKS + R] = v1;
        }
    }
    __syncthreads();

    // masked softmax over r: warp h handles head h
    {
        int h = tid >> 5;
        float vals[16];
        float mx = -FLT_MAX;
#pragma unroll
        for (int j = 0; j < 16; j++) {
            int r = lane + 32 * j;
            float v = (msk[r] != 0) ? qk[h * QKS + r] : -FLT_MAX;
            vals[j] = v;
            mx = fmaxf(mx, v);
        }
#pragma unroll
        for (int s = 16; s; s >>= 1) mx = fmaxf(mx, __shfl_xor_sync(0xffffffffu, mx, s));
        float sum = 0.f;
#pragma unroll
        for (int j = 0; j < 16; j++) {
            int r = lane + 32 * j;
            float e = (msk[r] != 0) ? __expf(vals[j] - mx) : 0.f;
            sum += e;
            qk[h * QKS + r] = e;
        }
#pragma unroll
        for (int s = 16; s; s >>= 1) sum += __shfl_xor_sync(0xffffffffu, sum, s);
        if (lane == 0) sinv[h] = 1.f / sum;
    }
    __syncthreads();

    // transposed write: out[r*6144 + c*8 + h] (32B contiguous per r)
#pragma unroll
    for (int k = 0; k < 16; k++) {
        int idx = tid + 256 * k;          // 512 r x 8 h
        int r = idx >> 3, h = idx & 7;
        out[(size_t)r * (C_DIM * H_DIM) + c * H_DIM + h] =
            qk[h * QKS + r] * sinv[h];
    }
}

// ---------------------------------------------------------------------------
extern "C" void kernel_launch(void* const* d_in, const int* in_sizes, int n_in,
                              void* d_out, int out_size) {
    const float* msa  = (const float*)d_in[0];
    const int*   mask = (const int*)d_in[1];
    const float* wq   = (const float*)d_in[2];
    const float* wk   = (const float*)d_in[3];
    float* out = (float*)d_out;

    const int smemQP   = (6 * 256 + 6 * 256 + 6 * 2048) * 4;                 // 61,440
    const int smemMain = (2 * TILE_F + 2048 + 8 * QKS + 2176 + 512 + 8) * 4; // 102,048
    cudaFuncSetAttribute(kQP,   cudaFuncAttributeMaxDynamicSharedMemorySize, smemQP);
    cudaFuncSetAttribute(kMain, cudaFuncAttributeMaxDynamicSharedMemorySize, smemMain);

    kQP<<<128, 256, smemQP>>>(msa, wq, wk);
    kMain<<<768, 256, smemMain>>>(msa, mask, out);
}

// round 7
// speedup vs baseline: 1.6265x; 1.0188x over previous
#include <cuda_runtime.h>
#include <stdint.h>
#include <math.h>
#include <float.h>

// Shapes (fixed): MSA_emb (1,512,768,256) f32; seq_mask (1,512) i32;
// Wq,Wk (256,256) f32; out (1,512,768,8,1) f32
#define R_DIM 512
#define C_DIM 768
#define H_DIM 8
static constexpr float SCALE = 0.17677669529663687f; // 1/sqrt(32)

typedef unsigned long long u64;

// P[c][e][h] (h-major: 8 head coeffs = one 32B chunk)
__device__ float g_P[C_DIM * 2048];

// ---- packed f32x2 helpers (b64 regs) ----
__device__ __forceinline__ u64 ffma2(u64 a, u64 b, u64 c) {
    u64 d;
    asm("fma.rn.f32x2 %0, %1, %2, %3;" : "=l"(d) : "l"(a), "l"(b), "l"(c));
    return d;
}
__device__ __forceinline__ u64 padd2(u64 a, u64 b) {
    u64 d;
    asm("add.rn.f32x2 %0, %1, %2;" : "=l"(d) : "l"(a), "l"(b));
    return d;
}
__device__ __forceinline__ u64 pack2(float x, float y) {
    u64 d; asm("mov.b64 %0, {%1, %2};" : "=l"(d) : "f"(x), "f"(y)); return d;
}
__device__ __forceinline__ void unpack2(u64 d, float& x, float& y) {
    asm("mov.b64 {%0, %1}, %2;" : "=f"(x), "=f"(y) : "l"(d));
}

// ---- mbarrier + bulk-copy (TMA) helpers ----
__device__ __forceinline__ void mbar_init(unsigned bar, unsigned cnt) {
    asm volatile("mbarrier.init.shared.b64 [%0], %1;" :: "r"(bar), "r"(cnt) : "memory");
}
__device__ __forceinline__ void mbar_expect_tx(unsigned bar, unsigned bytes) {
    asm volatile("mbarrier.arrive.expect_tx.shared.b64 _, [%0], %1;"
                 :: "r"(bar), "r"(bytes) : "memory");
}
__device__ __forceinline__ void mbar_wait(unsigned bar, unsigned phase) {
    asm volatile(
        "{\n\t.reg .pred P;\n\t"
        "WL_%=:\n\t"
        "mbarrier.try_wait.parity.shared.b64 P, [%0], %1;\n\t"
        "@!P bra WL_%=;\n\t}"
        :: "r"(bar), "r"(phase) : "memory");
}
__device__ __forceinline__ void bulk_g2s(unsigned dst, const void* src,
                                         unsigned bytes, unsigned bar) {
    asm volatile(
        "cp.async.bulk.shared::cluster.global.mbarrier::complete_tx::bytes "
        "[%0], [%1], %2, [%3];"
        :: "r"(dst), "l"(src), "r"(bytes), "r"(bar) : "memory");
}

// ---------------------------------------------------------------------------
// kQP: Q = SCALE*(msa0 @ Wq^T); P[c][e][h] = sum_d Q[c][h*32+d]*Wk[h*32+d][e]
// grid 128 (6 c per block), 256 threads. Wk staged per-head through smem
// with register double-buffering (8 independent LDG.128 per thread per head).
// ---------------------------------------------------------------------------
__global__ void __launch_bounds__(256) kQP(const float* __restrict__ msa,
                                           const float* __restrict__ wq,
                                           const float* __restrict__ wk) {
    extern __shared__ float smq[];
    float* xs   = smq;             // [6][256]   = 1536
    float* qs   = xs + 6 * 256;    // [6][256]   = 1536
    float* ws   = qs + 6 * 256;    // [32][256]  = 8192 (one head slice of Wk)
    float* pbuf = ws + 8192;       // [6][2048]  = 12288
    const int c0  = blockIdx.x * 6;
    const int tid = threadIdx.x;

    for (int i = tid; i < 6 * 64; i += 256) {
        int cc = i >> 6, f4 = i & 63;
        reinterpret_cast<float4*>(&xs[cc * 256 + f4 * 4])[0] =
            reinterpret_cast<const float4*>(msa + (size_t)(c0 + cc) * 256)[f4];
    }
    __syncthreads();

    {   // Q: thread = output o = tid
        float acc[6] = {0, 0, 0, 0, 0, 0};
        const float4* wrow = reinterpret_cast<const float4*>(wq + (size_t)tid * 256);
#pragma unroll 8
        for (int f4 = 0; f4 < 64; f4++) {
            float4 w = __ldg(&wrow[f4]);
#pragma unroll
            for (int cc = 0; cc < 6; cc++) {
                const float* x = &xs[cc * 256 + f4 * 4];
                acc[cc] += w.x * x[0] + w.y * x[1] + w.z * x[2] + w.w * x[3];
            }
        }
#pragma unroll
        for (int cc = 0; cc < 6; cc++) qs[cc * 256 + tid] = acc[cc] * SCALE;
    }

    // P stage: per-head Wk slice via smem; next slice prefetched into regs
    const float4* wk4 = reinterpret_cast<const float4*>(wk);
    float4* ws4 = reinterpret_cast<float4*>(ws);
    float4 r[8];
#pragma unroll
    for (int i = 0; i < 8; i++) r[i] = __ldg(&wk4[tid + i * 256]);  // h=0 slice

    for (int h = 0; h < 8; h++) {
        __syncthreads();   // previous slice fully consumed (also covers qs on h=0)
#pragma unroll
        for (int i = 0; i < 8; i++) ws4[tid + i * 256] = r[i];
        __syncthreads();
        if (h < 7) {
#pragma unroll
            for (int i = 0; i < 8; i++)
                r[i] = __ldg(&wk4[(h + 1) * 2048 + tid + i * 256]);
        }
        // w column for this thread's e (= tid), all 32 d
        float w[32];
#pragma unroll
        for (int d = 0; d < 32; d++) w[d] = ws[d * 256 + tid];
#pragma unroll
        for (int cc = 0; cc < 6; cc++) {
            const float4* q4 = reinterpret_cast<const float4*>(qs + cc * 256 + h * 32);
            float a = 0.f;
#pragma unroll
            for (int j = 0; j < 8; j++) {
                float4 qv = q4[j];
                a += qv.x * w[4 * j] + qv.y * w[4 * j + 1] +
                     qv.z * w[4 * j + 2] + qv.w * w[4 * j + 3];
            }
            pbuf[cc * 2048 + tid * 8 + h] = a;
        }
    }
    __syncthreads();

    float4* gp = reinterpret_cast<float4*>(g_P + (size_t)c0 * 2048);
    const float4* pb = reinterpret_cast<const float4*>(pbuf);
    for (int i = tid; i < 3072; i += 256) gp[i] = pb[i];
}

// ---------------------------------------------------------------------------
// kMain: block per c. 16 tiles x 32 rows, double-buffered via cp.async.bulk
// (32 x 1KB row copies per tile, mbarrier completion). Thread = (row = tid&31,
// e-eighth = tid>>5), packed f32x2 over head pairs, partial combine, masked
// softmax, transposed write. 768 blocks, 256 threads, smem 102,064 B.
// ---------------------------------------------------------------------------
static constexpr int XS_STRIDE = 260;    // 1040B row stride: 16B-aligned, conflict-free
static constexpr int QKS = 516;
static constexpr int TILE_F = 32 * XS_STRIDE;  // 8320 floats per buffer

__global__ void __launch_bounds__(256) kMain(const float* __restrict__ msa,
                                             const int* __restrict__ mask,
                                             float* __restrict__ out) {
    extern __shared__ float sm[];
    float* xs   = sm;                       // 2 * 8320
    float* ps   = sm + 2 * TILE_F;          // 2048
    float* qk   = ps + 2048;                // 8*516 = 4128
    u64*   part = (u64*)(qk + 8 * QKS);     // 32*34 u64 = 2176 floats (16B aligned)
    int*   msk  = (int*)(qk + 8 * QKS + 2176); // 512
    float* sinv = (float*)(msk + 512);      // 8
    // mbarriers: 2 x 8B right after sinv (8B aligned)
    const unsigned mb0 = (unsigned)__cvta_generic_to_shared(sinv + 8);
    const unsigned mb1 = mb0 + 8;

    const int c    = blockIdx.x;
    const int tid  = threadIdx.x;
    const int lane = tid & 31;
    const int row  = tid & 31;   // row within tile
    const int eq   = tid >> 5;   // e-eighth (warp-uniform)

    const unsigned xs_s = (unsigned)__cvta_generic_to_shared(xs);

    if (tid == 0) { mbar_init(mb0, 32); mbar_init(mb1, 32); }
    __syncthreads();

    // prefetch tiles 0,1: 32 threads, one 1KB row each, per stage
    if (tid < 32) {
#pragma unroll
        for (int t = 0; t < 2; t++) {
            unsigned bar = t ? mb1 : mb0;
            mbar_expect_tx(bar, 1024);
            bulk_g2s(xs_s + (unsigned)((t * TILE_F + tid * XS_STRIDE) * 4),
                     msa + ((size_t)(t * 32 + tid) * C_DIM + c) * 256,
                     1024, bar);
        }
    }
    {   // P slice + mask (overlaps with TMA)
        float4* p4 = reinterpret_cast<float4*>(ps);
        const float4* g4 = reinterpret_cast<const float4*>(g_P + (size_t)c * 2048);
        for (int i = tid; i < 512; i += 256) p4[i] = g4[i];
        for (int i = tid; i < 512; i += 256) msk[i] = mask[i];
    }

    const ulonglong2* pd = reinterpret_cast<const ulonglong2*>(ps);

    for (int t = 0; t < 16; t++) {
        const unsigned bar = (t & 1) ? mb1 : mb0;
        mbar_wait(bar, (t >> 1) & 1);
        __syncthreads();   // part WAR: prior combine readers done before new writes

        // partial QK for (row, e in [eq*32, eq*32+32))
        const float* xrow = xs + (t & 1) * TILE_F + row * XS_STRIDE + eq * 32;
        const float4* x4 = reinterpret_cast<const float4*>(xrow);
        u64 a0 = 0, a1 = 0, a2 = 0, a3 = 0;   // (+0.0f, +0.0f) pairs
#pragma unroll
        for (int i = 0; i < 8; i++) {
            float4 xv = x4[i];
            int e0 = eq * 32 + i * 4;
            {
                ulonglong2 pA = pd[e0 * 2], pB = pd[e0 * 2 + 1];
                u64 dx = pack2(xv.x, xv.x);
                a0 = ffma2(pA.x, dx, a0); a1 = ffma2(pA.y, dx, a1);
                a2 = ffma2(pB.x, dx, a2); a3 = ffma2(pB.y, dx, a3);
            }
            {
                ulonglong2 pA = pd[(e0 + 1) * 2], pB = pd[(e0 + 1) * 2 + 1];
                u64 dx = pack2(xv.y, xv.y);
                a0 = ffma2(pA.x, dx, a0); a1 = ffma2(pA.y, dx, a1);
                a2 = ffma2(pB.x, dx, a2); a3 = ffma2(pB.y, dx, a3);
            }
            {
                ulonglong2 pA = pd[(e0 + 2) * 2], pB = pd[(e0 + 2) * 2 + 1];
                u64 dx = pack2(xv.z, xv.z);
                a0 = ffma2(pA.x, dx, a0); a1 = ffma2(pA.y, dx, a1);
                a2 = ffma2(pB.x, dx, a2); a3 = ffma2(pB.y, dx, a3);
            }
            {
                ulonglong2 pA = pd[(e0 + 3) * 2], pB = pd[(e0 + 3) * 2 + 1];
                u64 dx = pack2(xv.w, xv.w);
                a0 = ffma2(pA.x, dx, a0); a1 = ffma2(pA.y, dx, a1);
                a2 = ffma2(pB.x, dx, a2); a3 = ffma2(pB.y, dx, a3);
            }
        }
        u64* pw = part + row * 34 + eq * 4;
        pw[0] = a0; pw[1] = a1; pw[2] = a2; pw[3] = a3;
        __syncthreads();   // xs consumed + part visible

        // refill the buffer just consumed with tile t+2
        if (t < 14 && tid < 32) {
            int tn = t + 2;
            mbar_expect_tx(bar, 1024);
            bulk_g2s(xs_s + (unsigned)(((tn & 1) * TILE_F + tid * XS_STRIDE) * 4),
                     msa + ((size_t)(tn * 32 + tid) * C_DIM + c) * 256,
                     1024, bar);
        }

        // combine 8 e-partials -> qk (128 threads: row x head-pair)
        if (tid < 128) {
            int rr = tid >> 2, p = tid & 3;
            const u64* pr = part + rr * 34 + p;
            u64 s = pr[0];
#pragma unroll
            for (int e2 = 1; e2 < 8; e2++) s = padd2(s, pr[e2 * 4]);
            float v0, v1;
            unpack2(s, v0, v1);
            int R = t * 32 + rr;
            qk[(2 * p) * QKS + R]     = v0;
            qk[(2 * p + 1) * QKS + R] = v1;
        }
    }
    __syncthreads();

    // masked softmax over r: warp h handles head h
    {
        int h = tid >> 5;
        float vals[16];
        float mx = -FLT_MAX;
#pragma unroll
        for (int j = 0; j < 16; j++) {
            int r = lane + 32 * j;
            float v = (msk[r] != 0) ? qk[h * QKS + r] : -FLT_MAX;
            vals[j] = v;
            mx = fmaxf(mx, v);
        }
#pragma unroll
        for (int s = 16; s; s >>= 1) mx = fmaxf(mx, __shfl_xor_sync(0xffffffffu, mx, s));
        float sum = 0.f;
#pragma unroll
        for (int j = 0; j < 16; j++) {
            int r = lane + 32 * j;
            float e = (msk[r] != 0) ? __expf(vals[j] - mx) : 0.f;
            sum += e;
            qk[h * QKS + r] = e;
        }
#pragma unroll
        for (int s = 16; s; s >>= 1) sum += __shfl_xor_sync(0xffffffffu, sum, s);
        if (lane == 0) sinv[h] = 1.f / sum;
    }
    __syncthreads();

    // transposed write: out[r*6144 + c*8 + h] (32B contiguous per r)
#pragma unroll
    for (int k = 0; k < 16; k++) {
        int idx = tid + 256 * k;          // 512 r x 8 h
        int r = idx >> 3, h = idx & 7;
        out[(size_t)r * (C_DIM * H_DIM) + c * H_DIM + h] =
            qk[h * QKS + r] * sinv[h];
    }
}

// ---------------------------------------------------------------------------
extern "C" void kernel_launch(void* const* d_in, const int* in_sizes, int n_in,
                              void* d_out, int out_size) {
    const float* msa  = (const float*)d_in[0];
    const int*   mask = (const int*)d_in[1];
    const float* wq   = (const float*)d_in[2];
    const float* wk   = (const float*)d_in[3];
    float* out = (float*)d_out;

    const int smemQP   = (6 * 256 + 6 * 256 + 8192 + 6 * 2048) * 4;              // 94,208
    const int smemMain = (2 * TILE_F + 2048 + 8 * QKS + 2176 + 512 + 8 + 4) * 4; // 102,064
    cudaFuncSetAttribute(kQP,   cudaFuncAttributeMaxDynamicSharedMemorySize, smemQP);
    cudaFuncSetAttribute(kMain, cudaFuncAttributeMaxDynamicSharedMemorySize, smemMain);

    kQP<<<128, 256, smemQP>>>(msa, wq, wk);
    kMain<<<768, 256, smemMain>>>(msa, mask, out);
}

// round 9
// speedup vs baseline: 1.6285x; 1.0012x over previous
#include <cuda_runtime.h>
#include <stdint.h>
#include <math.h>
#include <float.h>

// Shapes (fixed): MSA_emb (1,512,768,256) f32; seq_mask (1,512) i32;
// Wq,Wk (256,256) f32; out (1,512,768,8,1) f32
#define R_DIM 512
#define C_DIM 768
#define H_DIM 8
static constexpr float SCALE = 0.17677669529663687f; // 1/sqrt(32)

typedef unsigned long long u64;

// P[c][e][h] (h-major: 8 head coeffs = one 32B chunk)
__device__ float g_P[C_DIM * 2048];

// ---- packed f32x2 helpers (b64 regs) ----
__device__ __forceinline__ u64 ffma2(u64 a, u64 b, u64 c) {
    u64 d;
    asm("fma.rn.f32x2 %0, %1, %2, %3;" : "=l"(d) : "l"(a), "l"(b), "l"(c));
    return d;
}
__device__ __forceinline__ u64 padd2(u64 a, u64 b) {
    u64 d;
    asm("add.rn.f32x2 %0, %1, %2;" : "=l"(d) : "l"(a), "l"(b));
    return d;
}
__device__ __forceinline__ u64 pack2(float x, float y) {
    u64 d; asm("mov.b64 %0, {%1, %2};" : "=l"(d) : "f"(x), "f"(y)); return d;
}
__device__ __forceinline__ void unpack2(u64 d, float& x, float& y) {
    asm("mov.b64 {%0, %1}, %2;" : "=f"(x), "=f"(y) : "l"(d));
}

// ---- mbarrier + bulk-copy (TMA) helpers ----
__device__ __forceinline__ void mbar_init(unsigned bar, unsigned cnt) {
    asm volatile("mbarrier.init.shared.b64 [%0], %1;" :: "r"(bar), "r"(cnt) : "memory");
}
__device__ __forceinline__ void mbar_expect_tx(unsigned bar, unsigned bytes) {
    asm volatile("mbarrier.arrive.expect_tx.shared.b64 _, [%0], %1;"
                 :: "r"(bar), "r"(bytes) : "memory");
}
__device__ __forceinline__ void mbar_wait(unsigned bar, unsigned phase) {
    asm volatile(
        "{\n\t.reg .pred P;\n\t"
        "WL_%=:\n\t"
        "mbarrier.try_wait.parity.shared.b64 P, [%0], %1;\n\t"
        "@!P bra WL_%=;\n\t}"
        :: "r"(bar), "r"(phase) : "memory");
}
__device__ __forceinline__ void bulk_g2s(unsigned dst, const void* src,
                                         unsigned bytes, unsigned bar) {
    asm volatile(
        "cp.async.bulk.shared::cluster.global.mbarrier::complete_tx::bytes "
        "[%0], [%1], %2, [%3];"
        :: "r"(dst), "l"(src), "r"(bytes), "r"(bar) : "memory");
}

// ---------------------------------------------------------------------------
// kQP: Q = SCALE*(msa0 @ Wq^T); P[c][e][h] = sum_d Q[c][h*32+d]*Wk[h*32+d][e]
// grid 128 (6 c per block), 256 threads. Wk staged per-head through smem
// with register double-buffering (8 independent LDG.128 per thread per head).
// ---------------------------------------------------------------------------
__global__ void __launch_bounds__(256) kQP(const float* __restrict__ msa,
                                           const float* __restrict__ wq,
                                           const float* __restrict__ wk) {
    extern __shared__ float smq[];
    float* xs   = smq;             // [6][256]   = 1536
    float* qs   = xs + 6 * 256;    // [6][256]   = 1536
    float* ws   = qs + 6 * 256;    // [32][256]  = 8192 (one head slice of Wk)
    float* pbuf = ws + 8192;       // [6][2048]  = 12288
    const int c0  = blockIdx.x * 6;
    const int tid = threadIdx.x;

    for (int i = tid; i < 6 * 64; i += 256) {
        int cc = i >> 6, f4 = i & 63;
        reinterpret_cast<float4*>(&xs[cc * 256 + f4 * 4])[0] =
            reinterpret_cast<const float4*>(msa + (size_t)(c0 + cc) * 256)[f4];
    }
    __syncthreads();

    {   // Q: thread = output o = tid
        float acc[6] = {0, 0, 0, 0, 0, 0};
        const float4* wrow = reinterpret_cast<const float4*>(wq + (size_t)tid * 256);
#pragma unroll 8
        for (int f4 = 0; f4 < 64; f4++) {
            float4 w = __ldg(&wrow[f4]);
#pragma unroll
            for (int cc = 0; cc < 6; cc++) {
                const float* x = &xs[cc * 256 + f4 * 4];
                acc[cc] += w.x * x[0] + w.y * x[1] + w.z * x[2] + w.w * x[3];
            }
        }
#pragma unroll
        for (int cc = 0; cc < 6; cc++) qs[cc * 256 + tid] = acc[cc] * SCALE;
    }

    // P stage: per-head Wk slice via smem; next slice prefetched into regs
    const float4* wk4 = reinterpret_cast<const float4*>(wk);
    float4* ws4 = reinterpret_cast<float4*>(ws);
    float4 r[8];
#pragma unroll
    for (int i = 0; i < 8; i++) r[i] = __ldg(&wk4[tid + i * 256]);  // h=0 slice

    for (int h = 0; h < 8; h++) {
        __syncthreads();   // previous slice fully consumed (also covers qs on h=0)
#pragma unroll
        for (int i = 0; i < 8; i++) ws4[tid + i * 256] = r[i];
        __syncthreads();
        if (h < 7) {
#pragma unroll
            for (int i = 0; i < 8; i++)
                r[i] = __ldg(&wk4[(h + 1) * 2048 + tid + i * 256]);
        }
        // w column for this thread's e (= tid), all 32 d
        float w[32];
#pragma unroll
        for (int d = 0; d < 32; d++) w[d] = ws[d * 256 + tid];
#pragma unroll
        for (int cc = 0; cc < 6; cc++) {
            const float4* q4 = reinterpret_cast<const float4*>(qs + cc * 256 + h * 32);
            float a = 0.f;
#pragma unroll
            for (int j = 0; j < 8; j++) {
                float4 qv = q4[j];
                a += qv.x * w[4 * j] + qv.y * w[4 * j + 1] +
                     qv.z * w[4 * j + 2] + qv.w * w[4 * j + 3];
            }
            pbuf[cc * 2048 + tid * 8 + h] = a;
        }
    }
    __syncthreads();

    float4* gp = reinterpret_cast<float4*>(g_P + (size_t)c0 * 2048);
    const float4* pb = reinterpret_cast<const float4*>(pbuf);
    for (int i = tid; i < 3072; i += 256) gp[i] = pb[i];
}

// ---------------------------------------------------------------------------
// kMain: block per c. 16 tiles x 32 rows, double-buffered via cp.async.bulk
// (32 x 1KB row copies per tile, mbarrier completion). Thread = (row = tid&31,
// e-eighth = tid>>5), packed f32x2 over head pairs, partial combine, masked
// softmax, transposed write. 768 blocks, 256 threads, smem 102,064 B.
// ---------------------------------------------------------------------------
static constexpr int XS_STRIDE = 260;    // 1040B row stride: 16B-aligned, conflict-free
static constexpr int QKS = 516;
static constexpr int TILE_F = 32 * XS_STRIDE;  // 8320 floats per buffer

__global__ void __launch_bounds__(256) kMain(const float* __restrict__ msa,
                                             const int* __restrict__ mask,
                                             float* __restrict__ out) {
    extern __shared__ float sm[];
    float* xs   = sm;                       // 2 * 8320
    float* ps   = sm + 2 * TILE_F;          // 2048
    float* qk   = ps + 2048;                // 8*516 = 4128
    u64*   part = (u64*)(qk + 8 * QKS);     // 32*34 u64 = 2176 floats (16B aligned)
    int*   msk  = (int*)(qk + 8 * QKS + 2176); // 512
    float* sinv = (float*)(msk + 512);      // 8
    // mbarriers: 2 x 8B right after sinv (8B aligned)
    const unsigned mb0 = (unsigned)__cvta_generic_to_shared(sinv + 8);
    const unsigned mb1 = mb0 + 8;

    const int c    = blockIdx.x;
    const int tid  = threadIdx.x;
    const int lane = tid & 31;
    const int row  = tid & 31;   // row within tile
    const int eq   = tid >> 5;   // e-eighth (warp-uniform)

    const unsigned xs_s = (unsigned)__cvta_generic_to_shared(xs);

    if (tid == 0) { mbar_init(mb0, 32); mbar_init(mb1, 32); }
    __syncthreads();

    // prefetch tiles 0,1: 32 threads, one 1KB row each, per stage
    if (tid < 32) {
#pragma unroll
        for (int t = 0; t < 2; t++) {
            unsigned bar = t ? mb1 : mb0;
            mbar_expect_tx(bar, 1024);
            bulk_g2s(xs_s + (unsigned)((t * TILE_F + tid * XS_STRIDE) * 4),
                     msa + ((size_t)(t * 32 + tid) * C_DIM + c) * 256,
                     1024, bar);
        }
    }
    {   // P slice + mask (overlaps with TMA)
        float4* p4 = reinterpret_cast<float4*>(ps);
        const float4* g4 = reinterpret_cast<const float4*>(g_P + (size_t)c * 2048);
        for (int i = tid; i < 512; i += 256) p4[i] = g4[i];
        for (int i = tid; i < 512; i += 256) msk[i] = mask[i];
    }

    const ulonglong2* pd = reinterpret_cast<const ulonglong2*>(ps);

    for (int t = 0; t < 16; t++) {
        const unsigned bar = (t & 1) ? mb1 : mb0;
        mbar_wait(bar, (t >> 1) & 1);
        __syncthreads();   // part WAR: prior combine readers done before new writes

        // partial QK for (row, e in [eq*32, eq*32+32))
        const float* xrow = xs + (t & 1) * TILE_F + row * XS_STRIDE + eq * 32;
        const float4* x4 = reinterpret_cast<const float4*>(xrow);
        u64 a0 = 0, a1 = 0, a2 = 0, a3 = 0;   // (+0.0f, +0.0f) pairs
#pragma unroll
        for (int i = 0; i < 8; i++) {
            float4 xv = x4[i];
            int e0 = eq * 32 + i * 4;
            {
                ulonglong2 pA = pd[e0 * 2], pB = pd[e0 * 2 + 1];
                u64 dx = pack2(xv.x, xv.x);
                a0 = ffma2(pA.x, dx, a0); a1 = ffma2(pA.y, dx, a1);
                a2 = ffma2(pB.x, dx, a2); a3 = ffma2(pB.y, dx, a3);
            }
            {
                ulonglong2 pA = pd[(e0 + 1) * 2], pB = pd[(e0 + 1) * 2 + 1];
                u64 dx = pack2(xv.y, xv.y);
                a0 = ffma2(pA.x, dx, a0); a1 = ffma2(pA.y, dx, a1);
                a2 = ffma2(pB.x, dx, a2); a3 = ffma2(pB.y, dx, a3);
            }
            {
                ulonglong2 pA = pd[(e0 + 2) * 2], pB = pd[(e0 + 2) * 2 + 1];
                u64 dx = pack2(xv.z, xv.z);
                a0 = ffma2(pA.x, dx, a0); a1 = ffma2(pA.y, dx, a1);
                a2 = ffma2(pB.x, dx, a2); a3 = ffma2(pB.y, dx, a3);
            }
            {
                ulonglong2 pA = pd[(e0 + 3) * 2], pB = pd[(e0 + 3) * 2 + 1];
                u64 dx = pack2(xv.w, xv.w);
                a0 = ffma2(pA.x, dx, a0); a1 = ffma2(pA.y, dx, a1);
                a2 = ffma2(pB.x, dx, a2); a3 = ffma2(pB.y, dx, a3);
            }
        }
        u64* pw = part + row * 34 + eq * 4;
        pw[0] = a0; pw[1] = a1; pw[2] = a2; pw[3] = a3;
        __syncthreads();   // xs consumed + part visible

        // refill the buffer just consumed with tile t+2
        if (t < 14 && tid < 32) {
            int tn = t + 2;
            mbar_expect_tx(bar, 1024);
            bulk_g2s(xs_s + (unsigned)(((tn & 1) * TILE_F + tid * XS_STRIDE) * 4),
                     msa + ((size_t)(tn * 32 + tid) * C_DIM + c) * 256,
                     1024, bar);
        }

        // combine 8 e-partials -> qk (128 threads: row x head-pair)
        if (tid < 128) {
            int rr = tid >> 2, p = tid & 3;
            const u64* pr = part + rr * 34 + p;
            u64 s = pr[0];
#pragma unroll
            for (int e2 = 1; e2 < 8; e2++) s = padd2(s, pr[e2 * 4]);
            float v0, v1;
            unpack2(s, v0, v1);
            int R = t * 32 + rr;
            qk[(2 * p) * QKS + R]     = v0;
            qk[(2 * p + 1) * QKS + R] = v1;
        }
    }
    __syncthreads();

    // masked softmax over r: warp h handles head h
    {
        int h = tid >> 5;
        float vals[16];
        float mx = -FLT_MAX;
#pragma unroll
        for (int j = 0; j < 16; j++) {
            int r = lane + 32 * j;
            float v = (msk[r] != 0) ? qk[h * QKS + r] : -FLT_MAX;
            vals[j] = v;
            mx = fmaxf(mx, v);
        }
#pragma unroll
        for (int s = 16; s; s >>= 1) mx = fmaxf(mx, __shfl_xor_sync(0xffffffffu, mx, s));
        float sum = 0.f;
#pragma unroll
        for (int j = 0; j < 16; j++) {
            int r = lane + 32 * j;
            float e = (msk[r] != 0) ? __expf(vals[j] - mx) : 0.f;
            sum += e;
            qk[h * QKS + r] = e;
        }
#pragma unroll
        for (int s = 16; s; s >>= 1) sum += __shfl_xor_sync(0xffffffffu, sum, s);
        if (lane == 0) sinv[h] = 1.f / sum;
    }
    __syncthreads();

    // transposed write: out[r*6144 + c*8 + h] (32B contiguous per r)
#pragma unroll
    for (int k = 0; k < 16; k++) {
        int idx = tid + 256 * k;          // 512 r x 8 h
        int r = idx >> 3, h = idx & 7;
        out[(size_t)r * (C_DIM * H_DIM) + c * H_DIM + h] =
            qk[h * QKS + r] * sinv[h];
    }
}

// ---------------------------------------------------------------------------
extern "C" void kernel_launch(void* const* d_in, const int* in_sizes, int n_in,
                              void* d_out, int out_size) {
    const float* msa  = (const float*)d_in[0];
    const int*   mask = (const int*)d_in[1];
    const float* wq   = (const float*)d_in[2];
    const float* wk   = (const float*)d_in[3];
    float* out = (float*)d_out;

    const int smemQP   = (6 * 256 + 6 * 256 + 8192 + 6 * 2048) * 4;              // 94,208
    const int smemMain = (2 * TILE_F + 2048 + 8 * QKS + 2176 + 512 + 8 + 4) * 4; // 102,064
    cudaFuncSetAttribute(kQP,   cudaFuncAttributeMaxDynamicSharedMemorySize, smemQP);
    cudaFuncSetAttribute(kMain, cudaFuncAttributeMaxDynamicSharedMemorySize, smemMain);

    kQP<<<128, 256, smemQP>>>(msa, wq, wk);
    kMain<<<768, 256, smemMain>>>(msa, mask, out);
}